// round 3
// baseline (speedup 1.0000x reference)
#include <cuda_runtime.h>
#include <cuda_bf16.h>
#include <cstdint>

// ---------------------------------------------------------------------------
// GAT layer. N=8192, IN_F=512, OUT_F=256.
// out = NEG * (colsum(h) - (adj>0) @ h),  h = x @ W, NEG = -9e15.
// (masked s1/s2 attention terms are ~1e-16 relative to NEG terms: dropped)
//
// NOTE: harness PTX target is plain compute_103 -> NO tcgen05/arch-specific
// instructions. Use portable mma.sync / ldmatrix / cp.async only.
// ---------------------------------------------------------------------------

#define NROWS   8192
#define IN_F    512
#define OUT_F   256
#define NEGC    (-9.0e15f)

// Static scratch (no allocations allowed)
__device__ unsigned short g_B[(size_t)(2 * OUT_F) * NROWS]; // [512][8192] bf16 hi/lo limbs of h^T
__device__ float          g_S[OUT_F];                       // colsum(h)

// ---------------------------------------------------------------------------
// helpers
// ---------------------------------------------------------------------------
__device__ __forceinline__ uint32_t smem_to_u32(const void* p) {
    uint32_t a;
    asm("{ .reg .u64 t; cvta.to.shared.u64 t, %1; cvt.u32.u64 %0, t; }" : "=r"(a) : "l"(p));
    return a;
}
__device__ __forceinline__ void cp_async16(uint32_t dst, const void* src) {
    asm volatile("cp.async.cg.shared.global [%0], [%1], 16;" :: "r"(dst), "l"(src));
}
__device__ __forceinline__ void cp_commit() { asm volatile("cp.async.commit_group;"); }
template <int N>
__device__ __forceinline__ void cp_wait() { asm volatile("cp.async.wait_group %0;" :: "n"(N)); }

__device__ __forceinline__ void ldsm_x4(uint32_t addr, uint32_t& r0, uint32_t& r1,
                                        uint32_t& r2, uint32_t& r3) {
    asm volatile("ldmatrix.sync.aligned.m8n8.x4.shared.b16 {%0,%1,%2,%3}, [%4];"
                 : "=r"(r0), "=r"(r1), "=r"(r2), "=r"(r3) : "r"(addr));
}
__device__ __forceinline__ void mma_bf16(float* c, const uint32_t* a, uint32_t b0, uint32_t b1) {
    asm volatile("mma.sync.aligned.m16n8k16.row.col.f32.bf16.bf16.f32 "
                 "{%0,%1,%2,%3}, {%4,%5,%6,%7}, {%8,%9}, {%0,%1,%2,%3};"
                 : "+f"(c[0]), "+f"(c[1]), "+f"(c[2]), "+f"(c[3])
                 : "r"(a[0]), "r"(a[1]), "r"(a[2]), "r"(a[3]), "r"(b0), "r"(b1));
}
// swizzled byte offset inside a [row][128B] tile
__device__ __forceinline__ uint32_t swz(uint32_t row, uint32_t col) {
    return row * 128u + (col ^ ((row & 7u) * 16u));
}

// ---------------------------------------------------------------------------
// Kernel 0: zero colsum
// ---------------------------------------------------------------------------
__global__ void zero_S_kernel() {
    if (threadIdx.x < OUT_F) g_S[threadIdx.x] = 0.0f;
}

// ---------------------------------------------------------------------------
// Kernel 1: h = x @ W (fp32 CUDA-core tiled GEMM).
// Emits colsum(h) via atomics and hi/lo bf16 limbs of h transposed into g_B:
// row = (k>>7)*256 + (k&127)  (+128 for lo limb), cols = j (node index).
// ---------------------------------------------------------------------------
__global__ void __launch_bounds__(256) gemm_h_kernel(const float* __restrict__ x,
                                                     const float* __restrict__ W) {
    __shared__ float xs[64 * 32];
    __shared__ float ws[32 * 64];
    __shared__ float ts[64 * 68];
    int tid = threadIdx.x;
    int j0 = blockIdx.x * 64, k0 = blockIdx.y * 64;
    int tx = tid & 15, ty = tid >> 4;
    float acc[4][4] = {};

    for (int kc = 0; kc < IN_F; kc += 32) {
        #pragma unroll
        for (int q = 0; q < 8; q++) {
            int lin = q * 256 + tid;
            int j = lin >> 5, kk = lin & 31;
            xs[lin] = x[(size_t)(j0 + j) * IN_F + kc + kk];
            int kk2 = lin >> 6, k2 = lin & 63;
            ws[lin] = W[(size_t)(kc + kk2) * OUT_F + k0 + k2];
        }
        __syncthreads();
        #pragma unroll
        for (int kk = 0; kk < 32; kk++) {
            float a0 = xs[(ty * 4 + 0) * 32 + kk];
            float a1 = xs[(ty * 4 + 1) * 32 + kk];
            float a2 = xs[(ty * 4 + 2) * 32 + kk];
            float a3 = xs[(ty * 4 + 3) * 32 + kk];
            float4 b = *(float4*)&ws[kk * 64 + tx * 4];
            acc[0][0] += a0 * b.x; acc[0][1] += a0 * b.y; acc[0][2] += a0 * b.z; acc[0][3] += a0 * b.w;
            acc[1][0] += a1 * b.x; acc[1][1] += a1 * b.y; acc[1][2] += a1 * b.z; acc[1][3] += a1 * b.w;
            acc[2][0] += a2 * b.x; acc[2][1] += a2 * b.y; acc[2][2] += a2 * b.z; acc[2][3] += a2 * b.w;
            acc[3][0] += a3 * b.x; acc[3][1] += a3 * b.y; acc[3][2] += a3 * b.z; acc[3][3] += a3 * b.w;
        }
        __syncthreads();
    }

    #pragma unroll
    for (int m = 0; m < 4; m++) {
        float s = acc[0][m] + acc[1][m] + acc[2][m] + acc[3][m];
        atomicAdd(&g_S[k0 + tx * 4 + m], s);
    }

    #pragma unroll
    for (int i = 0; i < 4; i++)
        #pragma unroll
        for (int m = 0; m < 4; m++)
            ts[(tx * 4 + m) * 68 + (ty * 4 + i)] = acc[i][m];
    __syncthreads();

    #pragma unroll
    for (int p = 0; p < 16; p++) {
        int lin = p * 256 + tid;
        int kl = lin >> 6, jl = lin & 63;
        float v = ts[kl * 68 + jl];
        int k = k0 + kl;
        int hi_row = ((k >> 7) << 8) + (k & 127);
        __nv_bfloat16 hb = __float2bfloat16(v);
        __nv_bfloat16 lb = __float2bfloat16(v - __bfloat162float(hb));
        g_B[(size_t)hi_row * NROWS + j0 + jl] = __bfloat16_as_ushort(hb);
        g_B[(size_t)(hi_row + 128) * NROWS + j0 + jl] = __bfloat16_as_ushort(lb);
    }
}

// ---------------------------------------------------------------------------
// Kernel 2: masked GEMM via mma.sync bf16 + fused convert + fused epilogue.
//
// Per CTA: D[128 rows, 128 out-cols] = A[128,8192] @ (Bhi+Blo)[128cols,8192]^T
// A is adj int32 loaded directly (register-staged), converted to bf16 {0,1}.
// B panel = 256 rows of g_B (hi rows 0-127, lo rows 128-255) via cp.async.
// Both limbs accumulate into the same fp32 accumulators.
// Epilogue: out = NEG * (S[k] - acc).
// Grid: (2 n-halves, 64 m-tiles). 256 threads = 8 warps (4 m x 2 n).
// ---------------------------------------------------------------------------
#define KC 64
#define A_TILE_B (128 * KC * 2)          // 16 KB
#define B_TILE_B (256 * KC * 2)          // 32 KB
#define SM_A0 0
#define SM_A1 A_TILE_B
#define SM_B0 (2 * A_TILE_B)
#define SM_B1 (2 * A_TILE_B + B_TILE_B)
#define GAT_SMEM (2 * A_TILE_B + 2 * B_TILE_B)   // 96 KB

struct AReg { int4 v[8]; };

__device__ __forceinline__ void load_A(AReg& ar, const int* __restrict__ adj,
                                       int m0, int it, int tid) {
    size_t kk = (size_t)it * KC;
    #pragma unroll
    for (int p = 0; p < 8; p++) {
        int c = p * 256 + tid;
        int row = c >> 4, kq = c & 15;
        ar.v[p] = *(const int4*)(adj + (size_t)(m0 + row) * NROWS + kk + kq * 4);
    }
}
__device__ __forceinline__ void store_A(const AReg& ar, char* smbase, int tid) {
    #pragma unroll
    for (int p = 0; p < 8; p++) {
        int c = p * 256 + tid;
        int row = c >> 4, kq = c & 15;
        int4 a = ar.v[p];
        uint32_t p0 = (a.x ? 0x3F80u : 0u) | ((a.y ? 0x3F80u : 0u) << 16);
        uint32_t p1 = (a.z ? 0x3F80u : 0u) | ((a.w ? 0x3F80u : 0u) << 16);
        *(uint2*)(smbase + swz(row, kq * 8u)) = make_uint2(p0, p1);
    }
}
__device__ __forceinline__ void cp_B(uint32_t smaddr, int n0, int it, int tid) {
    size_t kk = (size_t)it * KC;
    #pragma unroll
    for (int p = 0; p < 8; p++) {
        int c = p * 256 + tid;
        int row = c >> 3, cx = c & 7;
        const void* src = g_B + (size_t)(n0 + row) * NROWS + kk + cx * 8;
        cp_async16(smaddr + swz(row, cx * 16u), src);
    }
}

__global__ void __launch_bounds__(256, 1) gat_gemm_kernel(const int* __restrict__ adj,
                                                          float* __restrict__ out) {
    extern __shared__ char sm[];
    uint32_t smb = smem_to_u32(sm);
    int tid = threadIdx.x;
    int l = tid & 31, w = tid >> 5;
    int mw = w & 3, nw = w >> 2;
    int nt = blockIdx.x;              // 0..1 (output col half)
    int m0 = blockIdx.y * 128;        // row tile
    int n0 = nt * 256;                // g_B row base (hi|lo panel)

    int g = l >> 3, lr = l & 7;

    // ldmatrix per-lane address components
    // A: tiles ordered (rows0-7,k0-7)(rows8-15,k0-7)(rows0-7,k8-15)(rows8-15,k8-15)
    uint32_t a_row = (uint32_t)(mw * 32 + (g & 1) * 8 + lr);
    uint32_t a_chalf = (uint32_t)((g >> 1) * 16);
    // B: tiles ordered (n0-7,k0-7)(n0-7,k8-15)(n8-15,k0-7)(n8-15,k8-15)
    uint32_t b_row = (uint32_t)(nw * 64 + (g >> 1) * 8 + lr);
    uint32_t b_chalf = (uint32_t)((g & 1) * 16);

    float acc[2][8][4];
    #pragma unroll
    for (int mf = 0; mf < 2; mf++)
        #pragma unroll
        for (int nf = 0; nf < 8; nf++)
            #pragma unroll
            for (int q = 0; q < 4; q++) acc[mf][nf][q] = 0.0f;

    const uint32_t Aoff[2] = {SM_A0, SM_A1};
    const uint32_t Boff[2] = {SM_B0, SM_B1};

    AReg ar;
    load_A(ar, adj, m0, 0, tid);
    cp_B(smb + SM_B0, n0, 0, tid);
    cp_commit();

    for (int it = 0; it < 128; ++it) {
        int buf = it & 1;
        store_A(ar, sm + Aoff[buf], tid);
        if (it + 1 < 128) {
            cp_B(smb + Boff[buf ^ 1], n0, it + 1, tid);
            cp_commit();
            load_A(ar, adj, m0, it + 1, tid);
            cp_wait<1>();
        } else {
            cp_wait<0>();
        }
        __syncthreads();

        uint32_t Ab = smb + Aoff[buf];
        uint32_t Bb = smb + Boff[buf];
        #pragma unroll
        for (int ks = 0; ks < 4; ks++) {
            uint32_t af[2][4];
            #pragma unroll
            for (int mf = 0; mf < 2; mf++) {
                uint32_t addr = Ab + (a_row + mf * 16u) * 128u +
                                (((uint32_t)(ks * 32) | a_chalf) ^ (lr * 16u));
                ldsm_x4(addr, af[mf][0], af[mf][1], af[mf][2], af[mf][3]);
            }
            #pragma unroll
            for (int panel = 0; panel < 2; panel++) {
                #pragma unroll
                for (int np = 0; np < 4; np++) {
                    uint32_t r0, r1, r2, r3;
                    uint32_t row = b_row + (uint32_t)(panel * 128 + np * 16);
                    uint32_t addr = Bb + row * 128u +
                                    (((uint32_t)(ks * 32) | b_chalf) ^ (lr * 16u));
                    ldsm_x4(addr, r0, r1, r2, r3);
                    #pragma unroll
                    for (int mf = 0; mf < 2; mf++) {
                        mma_bf16(acc[mf][np * 2 + 0], af[mf], r0, r1);
                        mma_bf16(acc[mf][np * 2 + 1], af[mf], r2, r3);
                    }
                }
            }
        }
        __syncthreads();
    }

    // epilogue: out = NEG * (S - acc)
    #pragma unroll
    for (int mf = 0; mf < 2; mf++) {
        int r0 = m0 + mw * 32 + mf * 16 + (l >> 2);
        #pragma unroll
        for (int nf = 0; nf < 8; nf++) {
            int col = nt * 128 + nw * 64 + nf * 8 + (l & 3) * 2;
            float s0 = g_S[col], s1 = g_S[col + 1];
            float2 v0 = make_float2(NEGC * (s0 - acc[mf][nf][0]), NEGC * (s1 - acc[mf][nf][1]));
            float2 v1 = make_float2(NEGC * (s0 - acc[mf][nf][2]), NEGC * (s1 - acc[mf][nf][3]));
            *(float2*)(out + (size_t)r0 * OUT_F + col) = v0;
            *(float2*)(out + (size_t)(r0 + 8) * OUT_F + col) = v1;
        }
    }
}

// ---------------------------------------------------------------------------
// Launch
// ---------------------------------------------------------------------------
extern "C" void kernel_launch(void* const* d_in, const int* in_sizes, int n_in,
                              void* d_out, int out_size) {
    const float* x   = (const float*)d_in[0];   // [8192, 512]
    const float* W   = (const float*)d_in[1];   // [512, 256]
    const int*   adj = (const int*)d_in[3];     // [8192, 8192]
    float* out = (float*)d_out;                 // [8192, 256]

    zero_S_kernel<<<1, 256>>>();
    gemm_h_kernel<<<dim3(NROWS / 64, OUT_F / 64), 256>>>(x, W);

    cudaFuncSetAttribute(gat_gemm_kernel, cudaFuncAttributeMaxDynamicSharedMemorySize,
                         GAT_SMEM);
    gat_gemm_kernel<<<dim3(2, NROWS / 128), 256, GAT_SMEM>>>(adj, out);
}